// round 3
// baseline (speedup 1.0000x reference)
#include <cuda_runtime.h>
#include <cuda_bf16.h>
#include <stdint.h>

#define TH 256
#define TM 64
#define HID 512
#define NIN 16
#define NOUT 136
#define NO2 160            // padded layer-2 output cols
#define H0S 520            // H0 row stride (bf16)
#define H1S 136            // H1 chunk row stride (bf16)
#define WRS 40             // weight slab row stride (bf16): 80B, conflict-free, 16B-aligned
#define WLO 13440          // byte offset of lo block inside a W buffer (168 rows * 80B)
#define WBUFB 26880        // bytes per W buffer (hi+lo)
#define NETS 137

#define XS_OFF  0
#define H0H_OFF 4096
#define H0L_OFF (H0H_OFF + 66560)
#define H1H_OFF (H0L_OFF + 66560)
#define H1L_OFF (H1H_OFF + 17408)
#define WB_OFF  (H1L_OFF + 17408)
#define SMEM_BYTES (WB_OFF + 2*WBUFB)   // 225792

// pre-split, pre-transposed weights: [n][k] bf16
__device__ __align__(16) __nv_bfloat16 g_W1hi[HID*HID];
__device__ __align__(16) __nv_bfloat16 g_W1lo[HID*HID];
__device__ __align__(16) __nv_bfloat16 g_W2hi[NO2*HID];
__device__ __align__(16) __nv_bfloat16 g_W2lo[NO2*HID];

__global__ void prep_weights(const float* __restrict__ W1,
                             const float* __restrict__ W2)
{
    int i = blockIdx.x * blockDim.x + threadIdx.x;
    if (i < HID*HID) {
        int n = i >> 9, k = i & 511;
        float v = W1[k*HID + n];
        __nv_bfloat16 h = __float2bfloat16(v);
        g_W1hi[n*HID + k] = h;
        g_W1lo[n*HID + k] = __float2bfloat16(v - __bfloat162float(h));
    }
    int j = i - HID*HID;
    if (j >= 0 && j < NO2*HID) {
        int n = j >> 9, k = j & 511;
        float v = (n < NOUT) ? W2[k*NOUT + n] : 0.0f;
        __nv_bfloat16 h = __float2bfloat16(v);
        g_W2hi[n*HID + k] = h;
        g_W2lo[n*HID + k] = __float2bfloat16(v - __bfloat162float(h));
    }
}

__device__ __forceinline__ void mma16816(float* d, const uint32_t* a,
                                         const uint32_t* b)
{
    asm volatile(
        "mma.sync.aligned.m16n8k16.row.col.f32.bf16.bf16.f32 "
        "{%0,%1,%2,%3}, {%4,%5,%6,%7}, {%8,%9}, {%0,%1,%2,%3};\n"
        : "+f"(d[0]), "+f"(d[1]), "+f"(d[2]), "+f"(d[3])
        : "r"(a[0]), "r"(a[1]), "r"(a[2]), "r"(a[3]),
          "r"(b[0]), "r"(b[1]));
}

__device__ __forceinline__ void ldsm4(uint32_t* r, uint32_t saddr)
{
    asm volatile("ldmatrix.sync.aligned.m8n8.x4.shared.b16 {%0,%1,%2,%3}, [%4];\n"
                 : "=r"(r[0]), "=r"(r[1]), "=r"(r[2]), "=r"(r[3])
                 : "r"(saddr));
}

__device__ __forceinline__ void cpa16(uint32_t dst, const void* src)
{
    asm volatile("cp.async.cg.shared.global [%0], [%1], 16;\n" :: "r"(dst), "l"(src));
}
__device__ __forceinline__ void cpa_commit() { asm volatile("cp.async.commit_group;\n"); }
__device__ __forceinline__ void cpa_wait1()  { asm volatile("cp.async.wait_group 1;\n"); }
__device__ __forceinline__ void cpa_wait0()  { asm volatile("cp.async.wait_group 0;\n"); }

__device__ __forceinline__ void split_store2(__nv_bfloat16* Hh, __nv_bfloat16* Hl,
                                             int idx, float v0, float v1)
{
    __nv_bfloat162 hp = __floats2bfloat162_rn(v0, v1);
    float r0 = v0 - __bfloat162float(hp.x);
    float r1 = v1 - __bfloat162float(hp.y);
    __nv_bfloat162 lp = __floats2bfloat162_rn(r0, r1);
    *(__nv_bfloat162*)(Hh + idx) = hp;
    *(__nv_bfloat162*)(Hl + idx) = lp;
}

// ---- slab staging via cp.async (16B granules) ----
__device__ __forceinline__ void stage_l1(int c, int s, uint32_t buf, int tid)
{
    const int n0 = c*128, k0 = s*32;
    #pragma unroll
    for (int it = 0; it < 4; it++) {
        int idx = it*TH + tid;                  // 0..1023
        int half = idx >> 9;                    // 0: hi, 1: lo
        int rem = idx & 511;
        int r = rem >> 2, q = rem & 3;
        const __nv_bfloat16* src = (half ? g_W1lo : g_W1hi) + (n0 + r)*HID + k0 + q*8;
        cpa16(buf + half*WLO + r*80 + q*16, src);
    }
}

__device__ __forceinline__ void stage_l2(int c, int s2, uint32_t buf, int tid)
{
    const int k0 = c*128 + s2*32;
    #pragma unroll
    for (int it = 0; it < 5; it++) {
        int idx = it*TH + tid;                  // 0..1279
        int half = (idx >= 640) ? 1 : 0;
        int rem = idx - half*640;
        int r = rem >> 2, q = rem & 3;          // r: 0..159
        const __nv_bfloat16* src = (half ? g_W2lo : g_W2hi) + r*HID + k0 + q*8;
        cpa16(buf + half*WLO + r*80 + q*16, src);
    }
}

__global__ __launch_bounds__(TH, 1)
void ptpd_mma_kernel(const float* __restrict__ pts,
                     const float* __restrict__ W0, const float* __restrict__ b0,
                     const float* __restrict__ b1, const float* __restrict__ b2,
                     float* __restrict__ out)
{
    extern __shared__ char sm[];
    float*          Xs  = (float*)(sm + XS_OFF);
    __nv_bfloat16*  H0h = (__nv_bfloat16*)(sm + H0H_OFF);
    __nv_bfloat16*  H0l = (__nv_bfloat16*)(sm + H0L_OFF);
    __nv_bfloat16*  H1h = (__nv_bfloat16*)(sm + H1H_OFF);
    __nv_bfloat16*  H1l = (__nv_bfloat16*)(sm + H1L_OFF);
    float*          netS = (float*)(sm + WB_OFF);

    const uint32_t smb  = (uint32_t)__cvta_generic_to_shared(sm);
    const uint32_t h0hS = smb + H0H_OFF;
    const uint32_t h0lS = smb + H0L_OFF;
    const uint32_t h1hS = smb + H1H_OFF;
    const uint32_t h1lS = smb + H1L_OFF;
    const uint32_t wbS  = smb + WB_OFF;

    const int tid  = threadIdx.x;
    const int lane = tid & 31;
    const int wid  = tid >> 5;
    const int g    = lane >> 2;
    const int t    = lane & 3;
    const int wm   = wid & 1;       // 2 m-warps, 32 rows each
    const int wn   = wid >> 1;      // 4 n-warps
    const long row0 = (long)blockIdx.x * TM;

    // ldmatrix address components
    const int arow = lane & 15;
    const int acol8 = (lane >> 4) << 3;
    const int brow = ((lane >> 4) << 3) + (lane & 7);
    const int bcol8 = lane & 8;

    // ---------------- X tile ----------------
    for (int i = tid; i < TM*NIN; i += TH)
        Xs[i] = pts[row0*NIN + i];
    __syncthreads();

    // prefetch slab 0 (overlaps layer 0 compute)
    stage_l1(0, 0, wbS, tid);
    cpa_commit();

    // ---------------- layer 0 (scalar) ----------------
    {
        const int c0 = tid, c1 = tid + 256;
        float w0a[NIN], w0b[NIN];
        #pragma unroll
        for (int k = 0; k < NIN; k++) {
            w0a[k] = W0[k*HID + c0];
            w0b[k] = W0[k*HID + c1];
        }
        const float ba = b0[c0], bb = b0[c1];
        for (int r = 0; r < TM; r++) {
            float a = ba, b = bb;
            #pragma unroll
            for (int k = 0; k < NIN; k++) {
                const float x = Xs[r*NIN + k];
                a = fmaf(x, w0a[k], a);
                b = fmaf(x, w0b[k], b);
            }
            a = tanhf(a); b = tanhf(b);
            __nv_bfloat16 ah = __float2bfloat16(a);
            H0h[r*H0S + c0] = ah;
            H0l[r*H0S + c0] = __float2bfloat16(a - __bfloat162float(ah));
            __nv_bfloat16 bh = __float2bfloat16(b);
            H0h[r*H0S + c1] = bh;
            H0l[r*H0S + c1] = __float2bfloat16(b - __bfloat162float(bh));
        }
    }

    // accumulators
    float acc1[2][4][4];
    float acc2[2][5][4];
    #pragma unroll
    for (int nt = 0; nt < 5; nt++) {
        int col = wn*40 + nt*8 + 2*t;
        float bv0 = (col     < NOUT) ? b2[col]     : 0.0f;
        float bv1 = (col + 1 < NOUT) ? b2[col + 1] : 0.0f;
        #pragma unroll
        for (int mt = 0; mt < 2; mt++) {
            acc2[mt][nt][0] = bv0; acc2[mt][nt][1] = bv1;
            acc2[mt][nt][2] = bv0; acc2[mt][nt][3] = bv1;
        }
    }

    // ============ flat 80-slab pipeline: per chunk c, 16 L1 slabs + 4 L2 slabs ============
    for (int G = 0; G < 80; G++) {
        const int c = G / 20, s = G % 20;
        const int nx = G + 1;
        if (nx < 80) {
            const int cn = nx / 20, sn = nx % 20;
            const uint32_t nb = wbS + (nx & 1)*WBUFB;
            if (sn < 16) stage_l1(cn, sn, nb, tid);
            else         stage_l2(cn, sn - 16, nb, tid);
            cpa_commit();
            cpa_wait1();
        } else {
            cpa_wait0();
        }
        __syncthreads();                         // slab G visible; prev compute done

        const uint32_t cb = wbS + (G & 1)*WBUFB;

        if (s == 0) {
            #pragma unroll
            for (int nt = 0; nt < 4; nt++) {
                int col = c*128 + wn*32 + nt*8 + 2*t;
                float bv0 = b1[col], bv1 = b1[col + 1];
                #pragma unroll
                for (int mt = 0; mt < 2; mt++) {
                    acc1[mt][nt][0] = bv0; acc1[mt][nt][1] = bv1;
                    acc1[mt][nt][2] = bv0; acc1[mt][nt][3] = bv1;
                }
            }
        }

        if (s < 16) {
            // ---- layer 1 slab: k = [s*32, +32) ----
            #pragma unroll
            for (int kt = 0; kt < 2; kt++) {
                const int kk = s*32 + kt*16;
                uint32_t ah[2][4], al[2][4];
                #pragma unroll
                for (int mt = 0; mt < 2; mt++) {
                    int ro = (wm*32 + mt*16 + arow)*H0S + kk + acol8;
                    ldsm4(ah[mt], h0hS + ro*2);
                    ldsm4(al[mt], h0lS + ro*2);
                }
                uint32_t bh[2][4], bl[2][4];
                #pragma unroll
                for (int np = 0; np < 2; np++) {
                    int bo = (wn*32 + np*16 + brow)*WRS + kt*16 + bcol8;
                    ldsm4(bh[np], cb + bo*2);
                    ldsm4(bl[np], cb + WLO + bo*2);
                }
                #pragma unroll
                for (int mt = 0; mt < 2; mt++)
                    #pragma unroll
                    for (int nt = 0; nt < 4; nt++) {
                        uint32_t* bhp = &bh[nt >> 1][(nt & 1)*2];
                        uint32_t* blp = &bl[nt >> 1][(nt & 1)*2];
                        mma16816(acc1[mt][nt], ah[mt], bhp);
                        mma16816(acc1[mt][nt], ah[mt], blp);
                        mma16816(acc1[mt][nt], al[mt], bhp);
                    }
            }
        } else {
            if (s == 16) {
                // ---- tanh + split -> H1 chunk (this chunk's 128 cols) ----
                #pragma unroll
                for (int mt = 0; mt < 2; mt++)
                    #pragma unroll
                    for (int nt = 0; nt < 4; nt++) {
                        int r   = wm*32 + mt*16 + g;
                        int col = wn*32 + nt*8 + 2*t;
                        split_store2(H1h, H1l, r*H1S + col,
                                     tanhf(acc1[mt][nt][0]), tanhf(acc1[mt][nt][1]));
                        split_store2(H1h, H1l, (r + 8)*H1S + col,
                                     tanhf(acc1[mt][nt][2]), tanhf(acc1[mt][nt][3]));
                    }
                __syncthreads();                 // H1 visible before L2 MMAs
            }
            // ---- layer 2 slab: local k = [(s-16)*32, +32) within chunk ----
            #pragma unroll
            for (int kt = 0; kt < 2; kt++) {
                const int kl = (s - 16)*32 + kt*16;
                uint32_t ah[2][4], al[2][4];
                #pragma unroll
                for (int mt = 0; mt < 2; mt++) {
                    int ro = (wm*32 + mt*16 + arow)*H1S + kl + acol8;
                    ldsm4(ah[mt], h1hS + ro*2);
                    ldsm4(al[mt], h1lS + ro*2);
                }
                uint32_t bh[3][4], bl[3][4];
                #pragma unroll
                for (int np = 0; np < 3; np++) {
                    int bo = (wn*40 + np*16 + brow)*WRS + kt*16 + bcol8;
                    ldsm4(bh[np], cb + bo*2);
                    ldsm4(bl[np], cb + WLO + bo*2);
                }
                #pragma unroll
                for (int mt = 0; mt < 2; mt++)
                    #pragma unroll
                    for (int nt = 0; nt < 5; nt++) {
                        uint32_t* bhp = &bh[nt >> 1][(nt & 1)*2];
                        uint32_t* blp = &bl[nt >> 1][(nt & 1)*2];
                        mma16816(acc2[mt][nt], ah[mt], bhp);
                        mma16816(acc2[mt][nt], ah[mt], blp);
                        mma16816(acc2[mt][nt], al[mt], bhp);
                    }
            }
        }
        __syncthreads();                         // compute(G) done before slab G+2 staging
    }

    // ---- net -> smem (overlays W buffers; last sync above protects) ----
    #pragma unroll
    for (int mt = 0; mt < 2; mt++)
        #pragma unroll
        for (int nt = 0; nt < 5; nt++) {
            int r   = wm*32 + mt*16 + g;
            int col = wn*40 + nt*8 + 2*t;
            if (col + 1 < NOUT) {
                netS[r*NETS + col]           = acc2[mt][nt][0];
                netS[r*NETS + col + 1]       = acc2[mt][nt][1];
                netS[(r + 8)*NETS + col]     = acc2[mt][nt][2];
                netS[(r + 8)*NETS + col + 1] = acc2[mt][nt][3];
            }
        }
    __syncthreads();

    // ---- quadratic form ----
    if (tid < TM) {
        const float* nn = netS + tid*NETS;
        const float* xv = Xs + tid*NIN;
        float x[NIN], sx = 0.0f;
        #pragma unroll
        for (int i = 0; i < NIN; i++) { x[i] = xv[i]; sx = fmaf(x[i], x[i], sx); }
        float y[NIN];
        #pragma unroll
        for (int j = 0; j < NIN; j++) y[j] = 0.0f;
        int tt = 0;
        #pragma unroll
        for (int i = 0; i < NIN; i++) {
            #pragma unroll
            for (int j = 0; j <= i; j++) {
                y[j] = fmaf(nn[tt], x[i], y[j]);
                tt++;
            }
        }
        float v = 0.0f;
        #pragma unroll
        for (int j = 0; j < NIN; j++) v = fmaf(y[j], y[j], v);
        out[row0 + tid] = v + 1e-6f * sx;
    }
}

extern "C" void kernel_launch(void* const* d_in, const int* in_sizes, int n_in,
                              void* d_out, int out_size)
{
    const float* pts = (const float*)d_in[0];
    const float* W0  = (const float*)d_in[1];
    const float* b0  = (const float*)d_in[2];
    const float* W1  = (const float*)d_in[3];
    const float* b1  = (const float*)d_in[4];
    const float* W2  = (const float*)d_in[5];
    const float* b2  = (const float*)d_in[6];
    float* out = (float*)d_out;

    const int B = in_sizes[0] / NIN;

    cudaFuncSetAttribute(ptpd_mma_kernel,
                         cudaFuncAttributeMaxDynamicSharedMemorySize, SMEM_BYTES);

    const int prep_elems = HID*HID + NO2*HID;
    prep_weights<<<(prep_elems + 255)/256, 256>>>(W1, W2);

    ptpd_mma_kernel<<<B/TM, TH, SMEM_BYTES>>>(pts, W0, b0, b1, b2, out);
}

// round 4
// speedup vs baseline: 1.5689x; 1.5689x over previous
#include <cuda_runtime.h>
#include <cuda_bf16.h>
#include <stdint.h>

#define TH 256
#define TM 64
#define HID 512
#define NIN 16
#define NOUT 136
#define HS 520              // H row stride (bf16): conflict-free for ldmatrix
#define NETS 137

#define XS_OFF  0
#define HH_OFF  4096
#define HL_OFF  (HH_OFF + 66560)        // 64*520*2
#define NET_OFF (HL_OFF + 66560)
#define SMEM_BYTES (NET_OFF + 35072)    // 172288

// fragment-ordered weights: [ks][ng][lane] -> {bhi0, bhi1, blo0, blo1}
__device__ __align__(16) uint4 g_W1f[32 * 64 * 32];   // 1 MB
__device__ __align__(16) uint4 g_W2f[32 * 20 * 32];   // 320 KB (N padded to 160)

__device__ __forceinline__ uint32_t pack_bf2(float a, float b)
{
    __nv_bfloat162 p = __floats2bfloat162_rn(a, b);
    return *(uint32_t*)&p;
}

__global__ void prep_weights(const float* __restrict__ W1,
                             const float* __restrict__ W2)
{
    int idx = blockIdx.x * blockDim.x + threadIdx.x;
    const int T1 = 32 * 64 * 32;
    const int T2 = 32 * 20 * 32;
    if (idx < T1) {
        int lane = idx & 31, ng = (idx >> 5) & 63, ks = idx >> 11;
        int g = lane >> 2, t = lane & 3;
        int n = ng * 8 + g;
        int k0 = ks * 16 + 2 * t;
        float v00 = W1[(k0    )*HID + n], v01 = W1[(k0 + 1)*HID + n];
        float v10 = W1[(k0 + 8)*HID + n], v11 = W1[(k0 + 9)*HID + n];
        float h00 = __bfloat162float(__float2bfloat16(v00));
        float h01 = __bfloat162float(__float2bfloat16(v01));
        float h10 = __bfloat162float(__float2bfloat16(v10));
        float h11 = __bfloat162float(__float2bfloat16(v11));
        uint4 o;
        o.x = pack_bf2(h00, h01);
        o.y = pack_bf2(h10, h11);
        o.z = pack_bf2(v00 - h00, v01 - h01);
        o.w = pack_bf2(v10 - h10, v11 - h11);
        g_W1f[idx] = o;
    } else if (idx < T1 + T2) {
        int j = idx - T1;
        int lane = j & 31, ng = (j >> 5) % 20, ks = j / (20 * 32);
        int g = lane >> 2, t = lane & 3;
        int n = ng * 8 + g;
        int k0 = ks * 16 + 2 * t;
        float v00 = (n < NOUT) ? W2[(k0    )*NOUT + n] : 0.0f;
        float v01 = (n < NOUT) ? W2[(k0 + 1)*NOUT + n] : 0.0f;
        float v10 = (n < NOUT) ? W2[(k0 + 8)*NOUT + n] : 0.0f;
        float v11 = (n < NOUT) ? W2[(k0 + 9)*NOUT + n] : 0.0f;
        float h00 = __bfloat162float(__float2bfloat16(v00));
        float h01 = __bfloat162float(__float2bfloat16(v01));
        float h10 = __bfloat162float(__float2bfloat16(v10));
        float h11 = __bfloat162float(__float2bfloat16(v11));
        uint4 o;
        o.x = pack_bf2(h00, h01);
        o.y = pack_bf2(h10, h11);
        o.z = pack_bf2(v00 - h00, v01 - h01);
        o.w = pack_bf2(v10 - h10, v11 - h11);
        g_W2f[j] = o;
    }
}

__device__ __forceinline__ void mma16816(float* d, const uint32_t* a,
                                         uint32_t b0, uint32_t b1)
{
    asm volatile(
        "mma.sync.aligned.m16n8k16.row.col.f32.bf16.bf16.f32 "
        "{%0,%1,%2,%3}, {%4,%5,%6,%7}, {%8,%9}, {%0,%1,%2,%3};\n"
        : "+f"(d[0]), "+f"(d[1]), "+f"(d[2]), "+f"(d[3])
        : "r"(a[0]), "r"(a[1]), "r"(a[2]), "r"(a[3]),
          "r"(b0), "r"(b1));
}

__device__ __forceinline__ void ldsm4(uint32_t* r, uint32_t saddr)
{
    asm volatile("ldmatrix.sync.aligned.m8n8.x4.shared.b16 {%0,%1,%2,%3}, [%4];\n"
                 : "=r"(r[0]), "=r"(r[1]), "=r"(r[2]), "=r"(r[3])
                 : "r"(saddr));
}

__device__ __forceinline__ void split_store2(__nv_bfloat16* Hh, __nv_bfloat16* Hl,
                                             int idx, float v0, float v1)
{
    __nv_bfloat162 hp = __floats2bfloat162_rn(v0, v1);
    float r0 = v0 - __bfloat162float(hp.x);
    float r1 = v1 - __bfloat162float(hp.y);
    __nv_bfloat162 lp = __floats2bfloat162_rn(r0, r1);
    *(__nv_bfloat162*)(Hh + idx) = hp;
    *(__nv_bfloat162*)(Hl + idx) = lp;
}

__global__ __launch_bounds__(TH, 1)
void ptpd_mma_kernel(const float* __restrict__ pts,
                     const float* __restrict__ W0, const float* __restrict__ b0,
                     const float* __restrict__ b1, const float* __restrict__ b2,
                     float* __restrict__ out)
{
    extern __shared__ char sm[];
    float*          Xs  = (float*)(sm + XS_OFF);
    __nv_bfloat16*  Hh  = (__nv_bfloat16*)(sm + HH_OFF);
    __nv_bfloat16*  Hl  = (__nv_bfloat16*)(sm + HL_OFF);
    float*          netS = (float*)(sm + NET_OFF);

    const uint32_t smb = (uint32_t)__cvta_generic_to_shared(sm);
    const uint32_t hhS = smb + HH_OFF;
    const uint32_t hlS = smb + HL_OFF;

    const int tid  = threadIdx.x;
    const int lane = tid & 31;
    const int wid  = tid >> 5;
    const int g    = lane >> 2;
    const int t    = lane & 3;
    const long row0 = (long)blockIdx.x * TM;

    const int arow  = lane & 15;
    const int acol8 = (lane >> 4) << 3;

    // ---------------- X tile ----------------
    for (int i = tid; i < TM*NIN; i += TH)
        Xs[i] = pts[row0*NIN + i];
    __syncthreads();

    // ---------------- layer 0 (scalar) ----------------
    {
        const int c0 = tid, c1 = tid + 256;
        float w0a[NIN], w0b[NIN];
        #pragma unroll
        for (int k = 0; k < NIN; k++) {
            w0a[k] = W0[k*HID + c0];
            w0b[k] = W0[k*HID + c1];
        }
        const float ba = b0[c0], bb = b0[c1];
        for (int r = 0; r < TM; r++) {
            float a = ba, b = bb;
            #pragma unroll
            for (int k = 0; k < NIN; k++) {
                const float x = Xs[r*NIN + k];
                a = fmaf(x, w0a[k], a);
                b = fmaf(x, w0b[k], b);
            }
            a = tanhf(a); b = tanhf(b);
            __nv_bfloat16 ah = __float2bfloat16(a);
            Hh[r*HS + c0] = ah;
            Hl[r*HS + c0] = __float2bfloat16(a - __bfloat162float(ah));
            __nv_bfloat16 bh = __float2bfloat16(b);
            Hh[r*HS + c1] = bh;
            Hl[r*HS + c1] = __float2bfloat16(b - __bfloat162float(bh));
        }
    }
    __syncthreads();

    // =============== layer 1: each warp owns 64 n-cols, all 64 rows ===============
    {
        float acc1[4][8][4];
        #pragma unroll
        for (int nt = 0; nt < 8; nt++) {
            int col = wid*64 + nt*8 + 2*t;
            float bv0 = b1[col], bv1 = b1[col + 1];
            #pragma unroll
            for (int mt = 0; mt < 4; mt++) {
                acc1[mt][nt][0] = bv0; acc1[mt][nt][1] = bv1;
                acc1[mt][nt][2] = bv0; acc1[mt][nt][3] = bv1;
            }
        }

        for (int ks = 0; ks < 32; ks++) {
            // B fragments first half (nt 0..3)
            uint4 bva[4];
            #pragma unroll
            for (int nt = 0; nt < 4; nt++)
                bva[nt] = g_W1f[(ks*64 + wid*8 + nt)*32 + lane];

            // A fragments (hi/lo, 4 m-tiles)
            uint32_t ah[4][4], al[4][4];
            #pragma unroll
            for (int mt = 0; mt < 4; mt++) {
                int ro = (mt*16 + arow)*HS + ks*16 + acol8;
                ldsm4(ah[mt], hhS + ro*2);
                ldsm4(al[mt], hlS + ro*2);
            }

            // B fragments second half (prefetched before first-half MMAs)
            uint4 bvb[4];
            #pragma unroll
            for (int nt = 0; nt < 4; nt++)
                bvb[nt] = g_W1f[(ks*64 + wid*8 + 4 + nt)*32 + lane];

            #pragma unroll
            for (int nt = 0; nt < 4; nt++)
                #pragma unroll
                for (int mt = 0; mt < 4; mt++) {
                    mma16816(acc1[mt][nt], ah[mt], bva[nt].x, bva[nt].y);
                    mma16816(acc1[mt][nt], ah[mt], bva[nt].z, bva[nt].w);
                    mma16816(acc1[mt][nt], al[mt], bva[nt].x, bva[nt].y);
                }
            #pragma unroll
            for (int nt = 0; nt < 4; nt++)
                #pragma unroll
                for (int mt = 0; mt < 4; mt++) {
                    mma16816(acc1[mt][nt + 4], ah[mt], bvb[nt].x, bvb[nt].y);
                    mma16816(acc1[mt][nt + 4], ah[mt], bvb[nt].z, bvb[nt].w);
                    mma16816(acc1[mt][nt + 4], al[mt], bvb[nt].x, bvb[nt].y);
                }
        }

        __syncthreads();    // everyone done READING H0 before overwrite

        // tanh + split -> H1 (overwrites H0 buffers)
        #pragma unroll
        for (int mt = 0; mt < 4; mt++)
            #pragma unroll
            for (int nt = 0; nt < 8; nt++) {
                int r   = mt*16 + g;
                int col = wid*64 + nt*8 + 2*t;
                split_store2(Hh, Hl, r*HS + col,
                             tanhf(acc1[mt][nt][0]), tanhf(acc1[mt][nt][1]));
                split_store2(Hh, Hl, (r + 8)*HS + col,
                             tanhf(acc1[mt][nt][2]), tanhf(acc1[mt][nt][3]));
            }
    }
    __syncthreads();

    // =============== layer 2: 2 m-warps x 4 n-warps (N padded 160) ===============
    {
        const int wm = wid & 1;
        const int wn = wid >> 1;
        float acc2[2][5][4];
        #pragma unroll
        for (int nt = 0; nt < 5; nt++) {
            int col = wn*40 + nt*8 + 2*t;
            float bv0 = (col     < NOUT) ? b2[col]     : 0.0f;
            float bv1 = (col + 1 < NOUT) ? b2[col + 1] : 0.0f;
            #pragma unroll
            for (int mt = 0; mt < 2; mt++) {
                acc2[mt][nt][0] = bv0; acc2[mt][nt][1] = bv1;
                acc2[mt][nt][2] = bv0; acc2[mt][nt][3] = bv1;
            }
        }

        for (int ks = 0; ks < 32; ks++) {
            uint4 bv[5];
            #pragma unroll
            for (int nt = 0; nt < 5; nt++)
                bv[nt] = g_W2f[(ks*20 + wn*5 + nt)*32 + lane];

            uint32_t ah[2][4], al[2][4];
            #pragma unroll
            for (int mt = 0; mt < 2; mt++) {
                int ro = (wm*32 + mt*16 + arow)*HS + ks*16 + acol8;
                ldsm4(ah[mt], hhS + ro*2);
                ldsm4(al[mt], hlS + ro*2);
            }

            #pragma unroll
            for (int nt = 0; nt < 5; nt++)
                #pragma unroll
                for (int mt = 0; mt < 2; mt++) {
                    mma16816(acc2[mt][nt], ah[mt], bv[nt].x, bv[nt].y);
                    mma16816(acc2[mt][nt], ah[mt], bv[nt].z, bv[nt].w);
                    mma16816(acc2[mt][nt], al[mt], bv[nt].x, bv[nt].y);
                }
        }

        // net -> smem
        #pragma unroll
        for (int mt = 0; mt < 2; mt++)
            #pragma unroll
            for (int nt = 0; nt < 5; nt++) {
                int r   = wm*32 + mt*16 + g;
                int col = wn*40 + nt*8 + 2*t;
                if (col + 1 < NOUT) {
                    netS[r*NETS + col]           = acc2[mt][nt][0];
                    netS[r*NETS + col + 1]       = acc2[mt][nt][1];
                    netS[(r + 8)*NETS + col]     = acc2[mt][nt][2];
                    netS[(r + 8)*NETS + col + 1] = acc2[mt][nt][3];
                }
            }
    }
    __syncthreads();

    // ---------------- quadratic form ----------------
    if (tid < TM) {
        const float* nn = netS + tid*NETS;
        const float* xv = Xs + tid*NIN;
        float x[NIN], sx = 0.0f;
        #pragma unroll
        for (int i = 0; i < NIN; i++) { x[i] = xv[i]; sx = fmaf(x[i], x[i], sx); }
        float y[NIN];
        #pragma unroll
        for (int j = 0; j < NIN; j++) y[j] = 0.0f;
        int tt = 0;
        #pragma unroll
        for (int i = 0; i < NIN; i++) {
            #pragma unroll
            for (int j = 0; j <= i; j++) {
                y[j] = fmaf(nn[tt], x[i], y[j]);
                tt++;
            }
        }
        float v = 0.0f;
        #pragma unroll
        for (int j = 0; j < NIN; j++) v = fmaf(y[j], y[j], v);
        out[row0 + tid] = v + 1e-6f * sx;
    }
}

extern "C" void kernel_launch(void* const* d_in, const int* in_sizes, int n_in,
                              void* d_out, int out_size)
{
    const float* pts = (const float*)d_in[0];
    const float* W0  = (const float*)d_in[1];
    const float* b0  = (const float*)d_in[2];
    const float* W1  = (const float*)d_in[3];
    const float* b1  = (const float*)d_in[4];
    const float* W2  = (const float*)d_in[5];
    const float* b2  = (const float*)d_in[6];
    float* out = (float*)d_out;

    const int B = in_sizes[0] / NIN;

    cudaFuncSetAttribute(ptpd_mma_kernel,
                         cudaFuncAttributeMaxDynamicSharedMemorySize, SMEM_BYTES);

    const int prep_threads = 32*64*32 + 32*20*32;
    prep_weights<<<(prep_threads + 255)/256, 256>>>(W1, W2);

    ptpd_mma_kernel<<<B/TM, TH, SMEM_BYTES>>>(pts, W0, b0, b1, b2, out);
}